// round 7
// baseline (speedup 1.0000x reference)
#include <cuda_runtime.h>
#include <cstdint>

#define N_NODES 50000
#define N_HALF  25000
#define N_EDGES 800000
#define D_IN 96
#define HID 128
#define SCAN_TPB 1024
#define SCAN_BLOCKS ((N_NODES + SCAN_TPB - 1) / SCAN_TPB)   // 49

// ---------------- scratch (device globals; no allocation allowed) ----------------
__device__ __align__(16) float g_buf0[N_NODES * HID];
__device__ __align__(16) float g_buf1[N_NODES * HID];
__device__ __align__(16) float g_buf2[N_NODES * HID];
__device__ __align__(16) float g_buf3[N_NODES * HID];
__device__ float g_dinv[N_NODES];
__device__ int   g_deg[N_NODES];
__device__ int   g_rowptr[N_NODES + 1];
__device__ int   g_cursor[N_NODES];
__device__ int   g_partials[SCAN_BLOCKS + 1];
__device__ __align__(8) int2 g_csr_sn[N_EDGES];   // .x = src, .y = norm (float bits)
__device__ __align__(8) int2 g_csr_se[N_EDGES];   // .x = src, .y = edge id

// ---------------- graph preprocessing ----------------
__global__ void zero_deg_kernel() {
    int i = blockIdx.x * blockDim.x + threadIdx.x;
    if (i < N_NODES) g_deg[i] = 0;
}

__global__ void hist_kernel(const int* __restrict__ dst) {
    int e = blockIdx.x * blockDim.x + threadIdx.x;
    if (e < N_EDGES) atomicAdd(&g_deg[dst[e]], 1);
}

__global__ void scan1_kernel() {
    __shared__ int ws[32];
    int gid = blockIdx.x * SCAN_TPB + threadIdx.x;
    int lane = threadIdx.x & 31, wid = threadIdx.x >> 5;
    int v = (gid < N_NODES) ? g_deg[gid] : 0;
    if (gid < N_NODES) g_dinv[gid] = rsqrtf((float)(v + 1));  // +1 self loop
    int x = v;
    #pragma unroll
    for (int off = 1; off < 32; off <<= 1) {
        int t = __shfl_up_sync(0xffffffff, x, off);
        if (lane >= off) x += t;
    }
    if (lane == 31) ws[wid] = x;
    __syncthreads();
    if (wid == 0) {
        int t = ws[lane];
        #pragma unroll
        for (int off = 1; off < 32; off <<= 1) {
            int u = __shfl_up_sync(0xffffffff, t, off);
            if (lane >= off) t += u;
        }
        ws[lane] = t;
    }
    __syncthreads();
    int excl = (wid ? ws[wid - 1] : 0) + x - v;
    if (gid < N_NODES) g_rowptr[gid] = excl;
    if (threadIdx.x == 0) g_partials[blockIdx.x] = ws[31];
}

__global__ void scan2_kernel() {
    int lane = threadIdx.x;
    int v0 = (lane < SCAN_BLOCKS) ? g_partials[lane] : 0;
    int v1 = (lane + 32 < SCAN_BLOCKS) ? g_partials[lane + 32] : 0;
    int x0 = v0;
    #pragma unroll
    for (int off = 1; off < 32; off <<= 1) {
        int t = __shfl_up_sync(0xffffffff, x0, off);
        if (lane >= off) x0 += t;
    }
    int tot0 = __shfl_sync(0xffffffff, x0, 31);
    int x1 = v1;
    #pragma unroll
    for (int off = 1; off < 32; off <<= 1) {
        int t = __shfl_up_sync(0xffffffff, x1, off);
        if (lane >= off) x1 += t;
    }
    if (lane < SCAN_BLOCKS) g_partials[lane] = x0 - v0;
    if (lane + 32 < SCAN_BLOCKS) g_partials[lane + 32] = tot0 + x1 - v1;
    if (lane == 31) g_rowptr[N_NODES] = tot0 + __shfl_sync(0xffffffff, x1, 31);
}

__global__ void scan3_kernel() {
    int gid = blockIdx.x * SCAN_TPB + threadIdx.x;
    if (gid < N_NODES) {
        int r = g_rowptr[gid] + g_partials[blockIdx.x];
        g_rowptr[gid] = r;
        g_cursor[gid] = r;
    }
}

__global__ void fill_kernel(const int* __restrict__ src, const int* __restrict__ dst) {
    int e = blockIdx.x * blockDim.x + threadIdx.x;
    if (e < N_EDGES) {
        int s = src[e], d = dst[e];
        int p = atomicAdd(&g_cursor[d], 1);
        float nm = g_dinv[s] * g_dinv[d];
        g_csr_sn[p] = make_int2(s, __float_as_int(nm));
        g_csr_se[p] = make_int2(s, e);
    }
}

// ---------------- tf32 mma.sync GEMM, double-buffered, row-range chunked ----------------
__device__ __forceinline__ uint32_t cvt_tf32(float f) {
    uint32_t r;
    asm("cvt.rna.tf32.f32 %0, %1;" : "=r"(r) : "f"(f));
    return r;
}

#define MMA_TF32(c, a, b)                                                      \
    asm volatile(                                                              \
        "mma.sync.aligned.m16n8k8.row.col.f32.tf32.tf32.f32 "                  \
        "{%0,%1,%2,%3}, {%4,%5,%6,%7}, {%8,%9}, {%0,%1,%2,%3};"                \
        : "+f"((c)[0]), "+f"((c)[1]), "+f"((c)[2]), "+f"((c)[3])               \
        : "r"((a)[0]), "r"((a)[1]), "r"((a)[2]), "r"((a)[3]),                  \
          "r"((b)[0]), "r"((b)[1]))

// Block tile 128x128, BK=16, 256 threads = 8 warps, warp tile 32(M) x 64(N).
// Computes rows [m_base, m_end).
template <int K>
__global__ void __launch_bounds__(256, 2) gemm_mma_kernel(
    const float* __restrict__ A, const float* __restrict__ W,
    const float* __restrict__ bias, float* __restrict__ C,
    int m_base, int m_end, int do_relu)
{
    __shared__ uint32_t As[2][128 * 20];
    __shared__ uint32_t Bs[2][16 * 136];
    const int tid = threadIdx.x;
    const int lane = tid & 31, wid = tid >> 5;
    const int gID = lane >> 2, t4 = lane & 3;
    const int wm = wid & 3, wn = wid >> 2;
    const int m0 = m_base + blockIdx.x * 128;
    constexpr int NC = K / 16;

    const int arow0 = tid >> 2;                 // 0..63
    const int acf   = (tid & 3) * 4;            // 0,4,8,12
    const int brow0 = tid >> 5;                 // 0..7
    const int bcf   = (tid & 31) * 4;           // 0..124

    float acc[2][8][4];
    #pragma unroll
    for (int mi = 0; mi < 2; mi++)
        #pragma unroll
        for (int ni = 0; ni < 8; ni++)
            #pragma unroll
            for (int j = 0; j < 4; j++) acc[mi][ni][j] = 0.f;

    float4 pa[2], pb[2];

    // prologue: load chunk 0
    {
        #pragma unroll
        for (int h = 0; h < 2; h++) {
            int g = m0 + arow0 + h * 64;
            pa[h] = make_float4(0.f, 0.f, 0.f, 0.f);
            if (g < m_end) pa[h] = *(const float4*)&A[(long)g * K + acf];
            pb[h] = *(const float4*)&W[(long)(brow0 + h * 8) * 128 + bcf];
        }
        #pragma unroll
        for (int h = 0; h < 2; h++) {
            uint32_t* p = &As[0][(arow0 + h * 64) * 20 + acf];
            p[0] = cvt_tf32(pa[h].x); p[1] = cvt_tf32(pa[h].y);
            p[2] = cvt_tf32(pa[h].z); p[3] = cvt_tf32(pa[h].w);
            uint32_t* q = &Bs[0][(brow0 + h * 8) * 136 + bcf];
            q[0] = cvt_tf32(pb[h].x); q[1] = cvt_tf32(pb[h].y);
            q[2] = cvt_tf32(pb[h].z); q[3] = cvt_tf32(pb[h].w);
        }
    }
    __syncthreads();

    #pragma unroll
    for (int c = 0; c < NC; c++) {
        const int cur = c & 1, nxt = cur ^ 1;
        if (c + 1 < NC) {
            int k0 = (c + 1) * 16;
            #pragma unroll
            for (int h = 0; h < 2; h++) {
                int g = m0 + arow0 + h * 64;
                pa[h] = make_float4(0.f, 0.f, 0.f, 0.f);
                if (g < m_end) pa[h] = *(const float4*)&A[(long)g * K + k0 + acf];
                pb[h] = *(const float4*)&W[(long)(k0 + brow0 + h * 8) * 128 + bcf];
            }
        }
        #pragma unroll
        for (int ks = 0; ks < 2; ks++) {
            uint32_t a[2][4], b[8][2];
            #pragma unroll
            for (int mi = 0; mi < 2; mi++) {
                int r = wm * 32 + mi * 16 + gID;
                int cc = ks * 8 + t4;
                a[mi][0] = As[cur][r * 20 + cc];
                a[mi][1] = As[cur][(r + 8) * 20 + cc];
                a[mi][2] = As[cur][r * 20 + cc + 4];
                a[mi][3] = As[cur][(r + 8) * 20 + cc + 4];
            }
            #pragma unroll
            for (int ni = 0; ni < 8; ni++) {
                int n  = wn * 64 + ni * 8 + gID;
                int kk = ks * 8 + t4;
                b[ni][0] = Bs[cur][kk * 136 + n];
                b[ni][1] = Bs[cur][(kk + 4) * 136 + n];
            }
            #pragma unroll
            for (int mi = 0; mi < 2; mi++)
                #pragma unroll
                for (int ni = 0; ni < 8; ni++)
                    MMA_TF32(acc[mi][ni], a[mi], b[ni]);
        }
        if (c + 1 < NC) {
            #pragma unroll
            for (int h = 0; h < 2; h++) {
                uint32_t* p = &As[nxt][(arow0 + h * 64) * 20 + acf];
                p[0] = cvt_tf32(pa[h].x); p[1] = cvt_tf32(pa[h].y);
                p[2] = cvt_tf32(pa[h].z); p[3] = cvt_tf32(pa[h].w);
                uint32_t* q = &Bs[nxt][(brow0 + h * 8) * 136 + bcf];
                q[0] = cvt_tf32(pb[h].x); q[1] = cvt_tf32(pb[h].y);
                q[2] = cvt_tf32(pb[h].z); q[3] = cvt_tf32(pb[h].w);
            }
            __syncthreads();
        }
    }

    // epilogue
    #pragma unroll
    for (int mi = 0; mi < 2; mi++) {
        int row = m0 + wm * 32 + mi * 16 + gID;
        #pragma unroll
        for (int ni = 0; ni < 8; ni++) {
            int col = wn * 64 + ni * 8 + t4 * 2;
            float bx = 0.f, by = 0.f;
            if (bias) { bx = bias[col]; by = bias[col + 1]; }
            float2 v0 = make_float2(acc[mi][ni][0] + bx, acc[mi][ni][1] + by);
            float2 v1 = make_float2(acc[mi][ni][2] + bx, acc[mi][ni][3] + by);
            if (do_relu) {
                v0.x = fmaxf(v0.x, 0.f); v0.y = fmaxf(v0.y, 0.f);
                v1.x = fmaxf(v1.x, 0.f); v1.y = fmaxf(v1.y, 0.f);
            }
            if (row < m_end)     *(float2*)&C[(long)row * 128 + col]       = v0;
            if (row + 8 < m_end) *(float2*)&C[(long)(row + 8) * 128 + col] = v1;
        }
    }
}

// ---------------- GCN aggregation: warp per node over [n0, n1) ----------------
__global__ void agg_kernel(const float* __restrict__ xw, const float* __restrict__ bias,
                           float* __restrict__ out, int n0, int n1) {
    int node = n0 + ((blockIdx.x * blockDim.x + threadIdx.x) >> 5);
    int lane = threadIdx.x & 31;
    if (node >= n1) return;
    const float4* xw4 = (const float4*)xw;
    float di = g_dinv[node];
    float sl = di * di;
    float4 v = xw4[node * 32 + lane];
    float4 acc = make_float4(v.x * sl, v.y * sl, v.z * sl, v.w * sl);
    int p    = g_rowptr[node];
    int pend = g_rowptr[node + 1];
    for (; p < pend; p++) {
        int2 sn = g_csr_sn[p];
        float nm = __int_as_float(sn.y);
        float4 u = xw4[sn.x * 32 + lane];
        acc.x += u.x * nm; acc.y += u.y * nm;
        acc.z += u.z * nm; acc.w += u.w * nm;
    }
    float4 b = ((const float4*)bias)[lane];
    acc.x = fmaxf(acc.x + b.x, 0.f);
    acc.y = fmaxf(acc.y + b.y, 0.f);
    acc.z = fmaxf(acc.z + b.z, 0.f);
    acc.w = fmaxf(acc.w + b.w, 0.f);
    ((float4*)out)[node * 32 + lane] = acc;
}

// ---------------- edge MLP: warp per dst-node over [n0, n1) ----------------
__global__ void edge_kernel(const float* __restrict__ Aarr, const float* __restrict__ Barr,
                            const float* __restrict__ Wm2, const float* __restrict__ bm2,
                            float* __restrict__ out, int n0, int n1) {
    int node = n0 + ((blockIdx.x * blockDim.x + threadIdx.x) >> 5);
    int lane = threadIdx.x & 31;
    if (node >= n1) return;
    int p    = g_rowptr[node];
    int pend = g_rowptr[node + 1];
    if (p == pend) return;
    float4 b = ((const float4*)Barr)[node * 32 + lane];
    float4 w = ((const float4*)Wm2)[lane];
    float bm = bm2[0];
    for (; p < pend; p++) {
        int2 se = g_csr_se[p];
        float4 a = ((const float4*)Aarr)[se.x * 32 + lane];
        float sum = fmaxf(a.x + b.x, 0.f) * w.x
                  + fmaxf(a.y + b.y, 0.f) * w.y
                  + fmaxf(a.z + b.z, 0.f) * w.z
                  + fmaxf(a.w + b.w, 0.f) * w.w;
        #pragma unroll
        for (int off = 16; off > 0; off >>= 1)
            sum += __shfl_down_sync(0xffffffff, sum, off);
        if (lane == 0) out[se.y] = sum + bm;
    }
}

// ---------------- launch ----------------
extern "C" void kernel_launch(void* const* d_in, const int* in_sizes, int n_in,
                              void* d_out, int out_size) {
    const float* x      = (const float*)d_in[0];
    const int*   eidx   = (const int*)d_in[1];
    const float* W_in   = (const float*)d_in[2];
    const float* b_in   = (const float*)d_in[3];
    const float* W1     = (const float*)d_in[4];
    const float* b1     = (const float*)d_in[5];
    const float* W2     = (const float*)d_in[6];
    const float* b2     = (const float*)d_in[7];
    const float* Wm1    = (const float*)d_in[8];
    const float* bm1    = (const float*)d_in[9];
    const float* Wm2    = (const float*)d_in[10];
    const float* bm2    = (const float*)d_in[11];
    float* out = (float*)d_out;

    const int* src = eidx;
    const int* dst = eidx + N_EDGES;

    float *buf0, *buf1, *buf2, *buf3;
    cudaGetSymbolAddress((void**)&buf0, g_buf0);
    cudaGetSymbolAddress((void**)&buf1, g_buf1);
    cudaGetSymbolAddress((void**)&buf2, g_buf2);
    cudaGetSymbolAddress((void**)&buf3, g_buf3);

    // streams + events (created once; no device allocation)
    static cudaStream_t sG = nullptr;                 // gather stream
    static cudaEvent_t evF = nullptr, evG1, evA1_0, evA1_1, evG2,
                       evA2_0, evA2_1, evE0, evE1, evEnd;
    if (!sG) {
        cudaStreamCreateWithFlags(&sG, cudaStreamNonBlocking);
        cudaEventCreateWithFlags(&evF,    cudaEventDisableTiming);
        cudaEventCreateWithFlags(&evG1,   cudaEventDisableTiming);
        cudaEventCreateWithFlags(&evA1_0, cudaEventDisableTiming);
        cudaEventCreateWithFlags(&evA1_1, cudaEventDisableTiming);
        cudaEventCreateWithFlags(&evG2,   cudaEventDisableTiming);
        cudaEventCreateWithFlags(&evA2_0, cudaEventDisableTiming);
        cudaEventCreateWithFlags(&evA2_1, cudaEventDisableTiming);
        cudaEventCreateWithFlags(&evE0,   cudaEventDisableTiming);
        cudaEventCreateWithFlags(&evE1,   cudaEventDisableTiming);
        cudaEventCreateWithFlags(&evEnd,  cudaEventDisableTiming);
    }

    const int TPB = 256;
    dim3 nodeGrid((N_NODES + TPB - 1) / TPB);
    dim3 edgeGrid((N_EDGES + TPB - 1) / TPB);
    dim3 gemmFull((N_NODES + 127) / 128);
    dim3 gemmHalf((N_HALF + 127) / 128);
    dim3 warpHalf((N_HALF * 32 + TPB - 1) / TPB);

    // ---- fork ----
    cudaEventRecord(evF, 0);
    cudaStreamWaitEvent(sG, evF, 0);

    // gather stream: CSR build
    zero_deg_kernel<<<nodeGrid, TPB, 0, sG>>>();
    hist_kernel<<<edgeGrid, TPB, 0, sG>>>(dst);
    scan1_kernel<<<SCAN_BLOCKS, SCAN_TPB, 0, sG>>>();
    scan2_kernel<<<1, 32, 0, sG>>>();
    scan3_kernel<<<SCAN_BLOCKS, SCAN_TPB, 0, sG>>>();
    fill_kernel<<<edgeGrid, TPB, 0, sG>>>(src, dst);

    // tensor stream: h0 = relu(x@W_in+b_in) -> buf0 ; xw1 = h0@W1 -> buf1
    gemm_mma_kernel<96><<<gemmFull, 256>>>(x, W_in, b_in, buf0, 0, N_NODES, 1);
    gemm_mma_kernel<128><<<gemmFull, 256>>>(buf0, W1, nullptr, buf1, 0, N_NODES, 0);
    cudaEventRecord(evG1, 0);

    // gather: h1 = relu(agg(xw1)+b1) -> buf2, in halves
    cudaStreamWaitEvent(sG, evG1, 0);
    agg_kernel<<<warpHalf, TPB, 0, sG>>>(buf1, b1, buf2, 0, N_HALF);
    cudaEventRecord(evA1_0, sG);
    agg_kernel<<<warpHalf, TPB, 0, sG>>>(buf1, b1, buf2, N_HALF, N_NODES);
    cudaEventRecord(evA1_1, sG);

    // tensor: xw2 = h1@W2 -> buf0, in halves chasing agg1
    cudaStreamWaitEvent(0, evA1_0, 0);
    gemm_mma_kernel<128><<<gemmHalf, 256>>>(buf2, W2, nullptr, buf0, 0, N_HALF, 0);
    cudaStreamWaitEvent(0, evA1_1, 0);
    gemm_mma_kernel<128><<<gemmHalf, 256>>>(buf2, W2, nullptr, buf0, N_HALF, N_NODES, 0);
    cudaEventRecord(evG2, 0);

    // gather: h2 = relu(agg(xw2)+b2) -> buf1, in halves
    cudaStreamWaitEvent(sG, evG2, 0);
    agg_kernel<<<warpHalf, TPB, 0, sG>>>(buf0, b2, buf1, 0, N_HALF);
    cudaEventRecord(evA2_0, sG);
    agg_kernel<<<warpHalf, TPB, 0, sG>>>(buf0, b2, buf1, N_HALF, N_NODES);
    cudaEventRecord(evA2_1, sG);

    // tensor: A = h2@Wm1a + bm1 -> buf0 ; B = h2@Wm1b -> buf3 ; order A0,B0,A1,B1
    cudaStreamWaitEvent(0, evA2_0, 0);
    gemm_mma_kernel<128><<<gemmHalf, 256>>>(buf1, Wm1, bm1, buf0, 0, N_HALF, 0);
    gemm_mma_kernel<128><<<gemmHalf, 256>>>(buf1, Wm1 + HID * HID, nullptr, buf3, 0, N_HALF, 0);
    cudaStreamWaitEvent(0, evA2_1, 0);
    gemm_mma_kernel<128><<<gemmHalf, 256>>>(buf1, Wm1, bm1, buf0, N_HALF, N_NODES, 0);
    cudaEventRecord(evE0, 0);   // covers A0, B0, A1
    gemm_mma_kernel<128><<<gemmHalf, 256>>>(buf1, Wm1 + HID * HID, nullptr, buf3, N_HALF, N_NODES, 0);
    cudaEventRecord(evE1, 0);   // covers everything

    // gather: logits per edge, halves by dst node (edge_h needs all A + B_h)
    cudaStreamWaitEvent(sG, evE0, 0);
    edge_kernel<<<warpHalf, TPB, 0, sG>>>(buf0, buf3, Wm2, bm2, out, 0, N_HALF);
    cudaStreamWaitEvent(sG, evE1, 0);
    edge_kernel<<<warpHalf, TPB, 0, sG>>>(buf0, buf3, Wm2, bm2, out, N_HALF, N_NODES);

    // ---- join back to origin stream ----
    cudaEventRecord(evEnd, sG);
    cudaStreamWaitEvent(0, evEnd, 0);
}

// round 8
// speedup vs baseline: 1.1662x; 1.1662x over previous
#include <cuda_runtime.h>
#include <cuda_fp16.h>
#include <cstdint>

#define N_NODES 50000
#define N_EDGES 800000
#define D_IN 96
#define HID 128
#define SCAN_TPB 1024
#define SCAN_BLOCKS ((N_NODES + SCAN_TPB - 1) / SCAN_TPB)   // 49

// ---------------- scratch (device globals; no allocation allowed) ----------------
__device__ __align__(16) float g_buf0[N_NODES * HID];   // also reused as half storage
__device__ __align__(16) float g_buf1[N_NODES * HID];
__device__ __align__(16) float g_buf2[N_NODES * HID];
__device__ __align__(16) float g_buf3[N_NODES * HID];
__device__ float g_dinv[N_NODES];
__device__ int   g_deg[N_NODES];
__device__ int   g_rowptr[N_NODES + 1];
__device__ int   g_cursor[N_NODES];
__device__ int   g_partials[SCAN_BLOCKS + 1];
__device__ __align__(8) int2 g_csr_sn[N_EDGES];   // .x = src, .y = norm (float bits)
__device__ __align__(8) int2 g_csr_se[N_EDGES];   // .x = src, .y = edge id

// ---------------- graph preprocessing ----------------
__global__ void zero_deg_kernel() {
    int i = blockIdx.x * blockDim.x + threadIdx.x;
    if (i < N_NODES) g_deg[i] = 0;
}

__global__ void hist_kernel(const int* __restrict__ dst) {
    int e = blockIdx.x * blockDim.x + threadIdx.x;
    if (e < N_EDGES) atomicAdd(&g_deg[dst[e]], 1);
}

__global__ void scan1_kernel() {
    __shared__ int ws[32];
    int gid = blockIdx.x * SCAN_TPB + threadIdx.x;
    int lane = threadIdx.x & 31, wid = threadIdx.x >> 5;
    int v = (gid < N_NODES) ? g_deg[gid] : 0;
    if (gid < N_NODES) g_dinv[gid] = rsqrtf((float)(v + 1));  // +1 self loop
    int x = v;
    #pragma unroll
    for (int off = 1; off < 32; off <<= 1) {
        int t = __shfl_up_sync(0xffffffff, x, off);
        if (lane >= off) x += t;
    }
    if (lane == 31) ws[wid] = x;
    __syncthreads();
    if (wid == 0) {
        int t = ws[lane];
        #pragma unroll
        for (int off = 1; off < 32; off <<= 1) {
            int u = __shfl_up_sync(0xffffffff, t, off);
            if (lane >= off) t += u;
        }
        ws[lane] = t;
    }
    __syncthreads();
    int excl = (wid ? ws[wid - 1] : 0) + x - v;
    if (gid < N_NODES) g_rowptr[gid] = excl;
    if (threadIdx.x == 0) g_partials[blockIdx.x] = ws[31];
}

__global__ void scan2_kernel() {
    int lane = threadIdx.x;
    int v0 = (lane < SCAN_BLOCKS) ? g_partials[lane] : 0;
    int v1 = (lane + 32 < SCAN_BLOCKS) ? g_partials[lane + 32] : 0;
    int x0 = v0;
    #pragma unroll
    for (int off = 1; off < 32; off <<= 1) {
        int t = __shfl_up_sync(0xffffffff, x0, off);
        if (lane >= off) x0 += t;
    }
    int tot0 = __shfl_sync(0xffffffff, x0, 31);
    int x1 = v1;
    #pragma unroll
    for (int off = 1; off < 32; off <<= 1) {
        int t = __shfl_up_sync(0xffffffff, x1, off);
        if (lane >= off) x1 += t;
    }
    if (lane < SCAN_BLOCKS) g_partials[lane] = x0 - v0;
    if (lane + 32 < SCAN_BLOCKS) g_partials[lane + 32] = tot0 + x1 - v1;
    if (lane == 31) g_rowptr[N_NODES] = tot0 + __shfl_sync(0xffffffff, x1, 31);
}

__global__ void scan3_kernel() {
    int gid = blockIdx.x * SCAN_TPB + threadIdx.x;
    if (gid < N_NODES) {
        int r = g_rowptr[gid] + g_partials[blockIdx.x];
        g_rowptr[gid] = r;
        g_cursor[gid] = r;
    }
}

__global__ void fill_kernel(const int* __restrict__ src, const int* __restrict__ dst) {
    int e = blockIdx.x * blockDim.x + threadIdx.x;
    if (e < N_EDGES) {
        int s = src[e], d = dst[e];
        int p = atomicAdd(&g_cursor[d], 1);
        float nm = g_dinv[s] * g_dinv[d];
        g_csr_sn[p] = make_int2(s, __float_as_int(nm));
        g_csr_se[p] = make_int2(s, e);
    }
}

// ---------------- tf32 mma.sync GEMM, double-buffered ----------------
__device__ __forceinline__ uint32_t cvt_tf32(float f) {
    uint32_t r;
    asm("cvt.rna.tf32.f32 %0, %1;" : "=r"(r) : "f"(f));
    return r;
}

#define MMA_TF32(c, a, b)                                                      \
    asm volatile(                                                              \
        "mma.sync.aligned.m16n8k8.row.col.f32.tf32.tf32.f32 "                  \
        "{%0,%1,%2,%3}, {%4,%5,%6,%7}, {%8,%9}, {%0,%1,%2,%3};"                \
        : "+f"((c)[0]), "+f"((c)[1]), "+f"((c)[2]), "+f"((c)[3])               \
        : "r"((a)[0]), "r"((a)[1]), "r"((a)[2]), "r"((a)[3]),                  \
          "r"((b)[0]), "r"((b)[1]))

// Block tile 128x128, BK=16, 256 threads = 8 warps, warp tile 32(M) x 64(N).
// If W1 != nullptr, blockIdx.y selects (W0,bias0,C0) vs (W1,bias1,C1).
// out_half: C is __half (dense [M,128] half), else float.
template <int K>
__global__ void __launch_bounds__(256, 2) gemm_mma_kernel(
    const float* __restrict__ A,
    const float* __restrict__ W0, const float* __restrict__ bias0, void* __restrict__ C0,
    const float* __restrict__ W1, const float* __restrict__ bias1, void* __restrict__ C1,
    int M, int do_relu, int out_half)
{
    const float* W    = (blockIdx.y == 0) ? W0 : W1;
    const float* bias = (blockIdx.y == 0) ? bias0 : bias1;
    void*        C    = (blockIdx.y == 0) ? C0 : C1;

    __shared__ uint32_t As[2][128 * 20];
    __shared__ uint32_t Bs[2][16 * 136];
    const int tid = threadIdx.x;
    const int lane = tid & 31, wid = tid >> 5;
    const int gID = lane >> 2, t4 = lane & 3;
    const int wm = wid & 3, wn = wid >> 2;
    const int m0 = blockIdx.x * 128;
    constexpr int NC = K / 16;

    const int arow0 = tid >> 2;                 // 0..63
    const int acf   = (tid & 3) * 4;            // 0,4,8,12
    const int brow0 = tid >> 5;                 // 0..7
    const int bcf   = (tid & 31) * 4;           // 0..124

    float acc[2][8][4];
    #pragma unroll
    for (int mi = 0; mi < 2; mi++)
        #pragma unroll
        for (int ni = 0; ni < 8; ni++)
            #pragma unroll
            for (int j = 0; j < 4; j++) acc[mi][ni][j] = 0.f;

    float4 pa[2], pb[2];

    // prologue: load chunk 0
    {
        #pragma unroll
        for (int h = 0; h < 2; h++) {
            int g = m0 + arow0 + h * 64;
            pa[h] = make_float4(0.f, 0.f, 0.f, 0.f);
            if (g < M) pa[h] = *(const float4*)&A[(long)g * K + acf];
            pb[h] = *(const float4*)&W[(long)(brow0 + h * 8) * 128 + bcf];
        }
        #pragma unroll
        for (int h = 0; h < 2; h++) {
            uint32_t* p = &As[0][(arow0 + h * 64) * 20 + acf];
            p[0] = cvt_tf32(pa[h].x); p[1] = cvt_tf32(pa[h].y);
            p[2] = cvt_tf32(pa[h].z); p[3] = cvt_tf32(pa[h].w);
            uint32_t* q = &Bs[0][(brow0 + h * 8) * 136 + bcf];
            q[0] = cvt_tf32(pb[h].x); q[1] = cvt_tf32(pb[h].y);
            q[2] = cvt_tf32(pb[h].z); q[3] = cvt_tf32(pb[h].w);
        }
    }
    __syncthreads();

    #pragma unroll
    for (int c = 0; c < NC; c++) {
        const int cur = c & 1, nxt = cur ^ 1;
        if (c + 1 < NC) {
            int k0 = (c + 1) * 16;
            #pragma unroll
            for (int h = 0; h < 2; h++) {
                int g = m0 + arow0 + h * 64;
                pa[h] = make_float4(0.f, 0.f, 0.f, 0.f);
                if (g < M) pa[h] = *(const float4*)&A[(long)g * K + k0 + acf];
                pb[h] = *(const float4*)&W[(long)(k0 + brow0 + h * 8) * 128 + bcf];
            }
        }
        #pragma unroll
        for (int ks = 0; ks < 2; ks++) {
            uint32_t a[2][4], b[8][2];
            #pragma unroll
            for (int mi = 0; mi < 2; mi++) {
                int r = wm * 32 + mi * 16 + gID;
                int cc = ks * 8 + t4;
                a[mi][0] = As[cur][r * 20 + cc];
                a[mi][1] = As[cur][(r + 8) * 20 + cc];
                a[mi][2] = As[cur][r * 20 + cc + 4];
                a[mi][3] = As[cur][(r + 8) * 20 + cc + 4];
            }
            #pragma unroll
            for (int ni = 0; ni < 8; ni++) {
                int n  = wn * 64 + ni * 8 + gID;
                int kk = ks * 8 + t4;
                b[ni][0] = Bs[cur][kk * 136 + n];
                b[ni][1] = Bs[cur][(kk + 4) * 136 + n];
            }
            #pragma unroll
            for (int mi = 0; mi < 2; mi++)
                #pragma unroll
                for (int ni = 0; ni < 8; ni++)
                    MMA_TF32(acc[mi][ni], a[mi], b[ni]);
        }
        if (c + 1 < NC) {
            #pragma unroll
            for (int h = 0; h < 2; h++) {
                uint32_t* p = &As[nxt][(arow0 + h * 64) * 20 + acf];
                p[0] = cvt_tf32(pa[h].x); p[1] = cvt_tf32(pa[h].y);
                p[2] = cvt_tf32(pa[h].z); p[3] = cvt_tf32(pa[h].w);
                uint32_t* q = &Bs[nxt][(brow0 + h * 8) * 136 + bcf];
                q[0] = cvt_tf32(pb[h].x); q[1] = cvt_tf32(pb[h].y);
                q[2] = cvt_tf32(pb[h].z); q[3] = cvt_tf32(pb[h].w);
            }
            __syncthreads();
        }
    }

    // epilogue
    #pragma unroll
    for (int mi = 0; mi < 2; mi++) {
        int row = m0 + wm * 32 + mi * 16 + gID;
        #pragma unroll
        for (int ni = 0; ni < 8; ni++) {
            int col = wn * 64 + ni * 8 + t4 * 2;
            float bx = 0.f, by = 0.f;
            if (bias) { bx = bias[col]; by = bias[col + 1]; }
            float2 v0 = make_float2(acc[mi][ni][0] + bx, acc[mi][ni][1] + by);
            float2 v1 = make_float2(acc[mi][ni][2] + bx, acc[mi][ni][3] + by);
            if (do_relu) {
                v0.x = fmaxf(v0.x, 0.f); v0.y = fmaxf(v0.y, 0.f);
                v1.x = fmaxf(v1.x, 0.f); v1.y = fmaxf(v1.y, 0.f);
            }
            if (out_half) {
                __half2* Ch = (__half2*)C;
                if (row < M)     Ch[((long)row * 128 + col) >> 1]       = __floats2half2_rn(v0.x, v0.y);
                if (row + 8 < M) Ch[((long)(row + 8) * 128 + col) >> 1] = __floats2half2_rn(v1.x, v1.y);
            } else {
                float* Cf = (float*)C;
                if (row < M)     *(float2*)&Cf[(long)row * 128 + col]       = v0;
                if (row + 8 < M) *(float2*)&Cf[(long)(row + 8) * 128 + col] = v1;
            }
        }
    }
}

// ---------------- GCN aggregation: warp per node, fp16 gather, fp32 accum ----------------
// xw: [N,128] half. Per lane: 4 features = 2 half2 = one uint2 (8B).
__global__ void agg_kernel(const __half2* __restrict__ xw, const float* __restrict__ bias,
                           float* __restrict__ out) {
    int node = (blockIdx.x * blockDim.x + threadIdx.x) >> 5;
    int lane = threadIdx.x & 31;
    if (node >= N_NODES) return;
    const uint2* xwv = (const uint2*)xw;
    float di = g_dinv[node];
    float sl = di * di;
    uint2 sv = xwv[node * 32 + lane];
    float2 s0 = __half22float2(*(__half2*)&sv.x);
    float2 s1 = __half22float2(*(__half2*)&sv.y);
    float4 acc = make_float4(s0.x * sl, s0.y * sl, s1.x * sl, s1.y * sl);
    int p    = g_rowptr[node];
    int pend = g_rowptr[node + 1];
    for (; p < pend; p++) {
        int2 sn = g_csr_sn[p];
        float nm = __int_as_float(sn.y);
        uint2 uv = xwv[sn.x * 32 + lane];
        float2 u0 = __half22float2(*(__half2*)&uv.x);
        float2 u1 = __half22float2(*(__half2*)&uv.y);
        acc.x += u0.x * nm; acc.y += u0.y * nm;
        acc.z += u1.x * nm; acc.w += u1.y * nm;
    }
    float4 b = ((const float4*)bias)[lane];
    acc.x = fmaxf(acc.x + b.x, 0.f);
    acc.y = fmaxf(acc.y + b.y, 0.f);
    acc.z = fmaxf(acc.z + b.z, 0.f);
    acc.w = fmaxf(acc.w + b.w, 0.f);
    ((float4*)out)[node * 32 + lane] = acc;
}

// ---------------- edge MLP: warp per dst-node over CSR; A,B in fp16 ----------------
__global__ void edge_kernel(const __half2* __restrict__ Ah, const __half2* __restrict__ Bh,
                            const float* __restrict__ Wm2, const float* __restrict__ bm2,
                            float* __restrict__ out) {
    int node = (blockIdx.x * blockDim.x + threadIdx.x) >> 5;
    int lane = threadIdx.x & 31;
    if (node >= N_NODES) return;
    int p    = g_rowptr[node];
    int pend = g_rowptr[node + 1];
    if (p == pend) return;
    const uint2* Av = (const uint2*)Ah;
    uint2 bv = ((const uint2*)Bh)[node * 32 + lane];
    float2 b0 = __half22float2(*(__half2*)&bv.x);
    float2 b1 = __half22float2(*(__half2*)&bv.y);
    float4 w = ((const float4*)Wm2)[lane];
    float bm = bm2[0];
    for (; p < pend; p++) {
        int2 se = g_csr_se[p];
        uint2 av = Av[se.x * 32 + lane];
        float2 a0 = __half22float2(*(__half2*)&av.x);
        float2 a1 = __half22float2(*(__half2*)&av.y);
        float sum = fmaxf(a0.x + b0.x, 0.f) * w.x
                  + fmaxf(a0.y + b0.y, 0.f) * w.y
                  + fmaxf(a1.x + b1.x, 0.f) * w.z
                  + fmaxf(a1.y + b1.y, 0.f) * w.w;
        #pragma unroll
        for (int off = 16; off > 0; off >>= 1)
            sum += __shfl_down_sync(0xffffffff, sum, off);
        if (lane == 0) out[se.y] = sum + bm;
    }
}

// ---------------- launch ----------------
extern "C" void kernel_launch(void* const* d_in, const int* in_sizes, int n_in,
                              void* d_out, int out_size) {
    const float* x      = (const float*)d_in[0];
    const int*   eidx   = (const int*)d_in[1];
    const float* W_in   = (const float*)d_in[2];
    const float* b_in   = (const float*)d_in[3];
    const float* W1     = (const float*)d_in[4];
    const float* b1     = (const float*)d_in[5];
    const float* W2     = (const float*)d_in[6];
    const float* b2     = (const float*)d_in[7];
    const float* Wm1    = (const float*)d_in[8];
    const float* bm1    = (const float*)d_in[9];
    const float* Wm2    = (const float*)d_in[10];
    const float* bm2    = (const float*)d_in[11];
    float* out = (float*)d_out;

    const int* src = eidx;
    const int* dst = eidx + N_EDGES;

    float *buf0, *buf1, *buf2, *buf3;
    cudaGetSymbolAddress((void**)&buf0, g_buf0);
    cudaGetSymbolAddress((void**)&buf1, g_buf1);
    cudaGetSymbolAddress((void**)&buf2, g_buf2);
    cudaGetSymbolAddress((void**)&buf3, g_buf3);

    static cudaStream_t s2 = nullptr;
    static cudaEvent_t evF = nullptr, evJ = nullptr;
    if (!s2) {
        cudaStreamCreateWithFlags(&s2, cudaStreamNonBlocking);
        cudaEventCreateWithFlags(&evF, cudaEventDisableTiming);
        cudaEventCreateWithFlags(&evJ, cudaEventDisableTiming);
    }

    const int TPB = 256;
    dim3 nodeGrid((N_NODES + TPB - 1) / TPB);
    dim3 edgeGrid((N_EDGES + TPB - 1) / TPB);
    dim3 gemmGrid((N_NODES + 127) / 128, 1);
    dim3 gemmGrid2((N_NODES + 127) / 128, 2);
    dim3 warpNodeGrid((N_NODES * 32 + TPB - 1) / TPB);

    // ---- fork: CSR build on s2, concurrent with GEMM1/GEMM2 ----
    cudaEventRecord(evF, 0);
    cudaStreamWaitEvent(s2, evF, 0);

    zero_deg_kernel<<<nodeGrid, TPB, 0, s2>>>();
    hist_kernel<<<edgeGrid, TPB, 0, s2>>>(dst);
    scan1_kernel<<<SCAN_BLOCKS, SCAN_TPB, 0, s2>>>();
    scan2_kernel<<<1, 32, 0, s2>>>();
    scan3_kernel<<<SCAN_BLOCKS, SCAN_TPB, 0, s2>>>();
    fill_kernel<<<edgeGrid, TPB, 0, s2>>>(src, dst);
    cudaEventRecord(evJ, s2);

    // main stream (serial — R7 showed cross-stream compute overlap doesn't pay):
    // h0 = relu(x @ W_in + b_in)            -> buf0 (fp32)
    gemm_mma_kernel<96><<<gemmGrid, 256>>>(x, W_in, b_in, buf0,
                                           nullptr, nullptr, nullptr, N_NODES, 1, 0);
    // xw1 = h0 @ W1                          -> buf1 (half)
    gemm_mma_kernel<128><<<gemmGrid, 256>>>(buf0, W1, nullptr, buf1,
                                            nullptr, nullptr, nullptr, N_NODES, 0, 1);

    // ---- join before first aggregation ----
    cudaStreamWaitEvent(0, evJ, 0);

    // h1 = relu(agg(xw1) + b1)               -> buf2 (fp32)
    agg_kernel<<<warpNodeGrid, TPB>>>((const __half2*)buf1, b1, buf2);
    // xw2 = h1 @ W2                          -> buf0 (half)
    gemm_mma_kernel<128><<<gemmGrid, 256>>>(buf2, W2, nullptr, buf0,
                                            nullptr, nullptr, nullptr, N_NODES, 0, 1);
    // h2 = relu(agg(xw2) + b2)               -> buf3 (fp32)
    agg_kernel<<<warpNodeGrid, TPB>>>((const __half2*)buf0, b2, buf3);
    // A = h2 @ Wm1[:128] + bm1 -> buf1 (half);  B = h2 @ Wm1[128:] -> buf2 (half)
    gemm_mma_kernel<128><<<gemmGrid2, 256>>>(buf3, Wm1, bm1, buf1,
                                             Wm1 + HID * HID, nullptr, buf2, N_NODES, 0, 1);
    // logits per edge (CSR-grouped by dst)
    edge_kernel<<<warpNodeGrid, TPB>>>((const __half2*)buf1, (const __half2*)buf2, Wm2, bm2, out);
}

// round 9
// speedup vs baseline: 1.2858x; 1.1026x over previous
#include <cuda_runtime.h>
#include <cuda_fp16.h>
#include <cstdint>

#define N_NODES 50000
#define N_EDGES 800000
#define D_IN 96
#define HID 128
#define SCAN_TPB 1024
#define SCAN_BLOCKS ((N_NODES + SCAN_TPB - 1) / SCAN_TPB)   // 49
#define HALF_OFF (N_NODES * HID)                            // halves per feature array

// ---------------- scratch (device globals; no allocation allowed) ----------------
// Each float buffer holds TWO half feature arrays (lo/hi).
__device__ __align__(16) float g_buf0[N_NODES * HID];
__device__ __align__(16) float g_buf1[N_NODES * HID];
__device__ __align__(16) float g_buf2[N_NODES * HID];
__device__ __align__(16) float g_buf3[N_NODES * HID];
__device__ __align__(16) __half g_wt_in[HID * D_IN];
__device__ __align__(16) __half g_wt1[HID * HID];
__device__ __align__(16) __half g_wt2[HID * HID];
__device__ __align__(16) __half g_wtm1a[HID * HID];
__device__ __align__(16) __half g_wtm1b[HID * HID];
__device__ float g_dinv[N_NODES];
__device__ int   g_deg[N_NODES];
__device__ int   g_rowptr[N_NODES + 1];
__device__ int   g_cursor[N_NODES];
__device__ int   g_partials[SCAN_BLOCKS + 1];
__device__ __align__(8) int2 g_csr_sn[N_EDGES];   // .x = src, .y = norm (float bits)
__device__ __align__(8) int2 g_csr_se[N_EDGES];   // .x = src, .y = edge id

// ---------------- graph preprocessing ----------------
__global__ void zero_deg_kernel() {
    int i = blockIdx.x * blockDim.x + threadIdx.x;
    if (i < N_NODES) g_deg[i] = 0;
}

__global__ void hist_kernel(const int* __restrict__ dst) {
    int e = blockIdx.x * blockDim.x + threadIdx.x;
    if (e < N_EDGES) atomicAdd(&g_deg[dst[e]], 1);
}

__global__ void scan1_kernel() {
    __shared__ int ws[32];
    int gid = blockIdx.x * SCAN_TPB + threadIdx.x;
    int lane = threadIdx.x & 31, wid = threadIdx.x >> 5;
    int v = (gid < N_NODES) ? g_deg[gid] : 0;
    if (gid < N_NODES) g_dinv[gid] = rsqrtf((float)(v + 1));  // +1 self loop
    int x = v;
    #pragma unroll
    for (int off = 1; off < 32; off <<= 1) {
        int t = __shfl_up_sync(0xffffffff, x, off);
        if (lane >= off) x += t;
    }
    if (lane == 31) ws[wid] = x;
    __syncthreads();
    if (wid == 0) {
        int t = ws[lane];
        #pragma unroll
        for (int off = 1; off < 32; off <<= 1) {
            int u = __shfl_up_sync(0xffffffff, t, off);
            if (lane >= off) t += u;
        }
        ws[lane] = t;
    }
    __syncthreads();
    int excl = (wid ? ws[wid - 1] : 0) + x - v;
    if (gid < N_NODES) g_rowptr[gid] = excl;
    if (threadIdx.x == 0) g_partials[blockIdx.x] = ws[31];
}

__global__ void scan2_kernel() {
    int lane = threadIdx.x;
    int v0 = (lane < SCAN_BLOCKS) ? g_partials[lane] : 0;
    int v1 = (lane + 32 < SCAN_BLOCKS) ? g_partials[lane + 32] : 0;
    int x0 = v0;
    #pragma unroll
    for (int off = 1; off < 32; off <<= 1) {
        int t = __shfl_up_sync(0xffffffff, x0, off);
        if (lane >= off) x0 += t;
    }
    int tot0 = __shfl_sync(0xffffffff, x0, 31);
    int x1 = v1;
    #pragma unroll
    for (int off = 1; off < 32; off <<= 1) {
        int t = __shfl_up_sync(0xffffffff, x1, off);
        if (lane >= off) x1 += t;
    }
    if (lane < SCAN_BLOCKS) g_partials[lane] = x0 - v0;
    if (lane + 32 < SCAN_BLOCKS) g_partials[lane + 32] = tot0 + x1 - v1;
    if (lane == 31) g_rowptr[N_NODES] = tot0 + __shfl_sync(0xffffffff, x1, 31);
}

__global__ void scan3_kernel() {
    int gid = blockIdx.x * SCAN_TPB + threadIdx.x;
    if (gid < N_NODES) {
        int r = g_rowptr[gid] + g_partials[blockIdx.x];
        g_rowptr[gid] = r;
        g_cursor[gid] = r;
    }
}

__global__ void fill_kernel(const int* __restrict__ src, const int* __restrict__ dst) {
    int e = blockIdx.x * blockDim.x + threadIdx.x;
    if (e < N_EDGES) {
        int s = src[e], d = dst[e];
        int p = atomicAdd(&g_cursor[d], 1);
        float nm = g_dinv[s] * g_dinv[d];
        g_csr_sn[p] = make_int2(s, __float_as_int(nm));
        g_csr_se[p] = make_int2(s, e);
    }
}

// ---------------- converts ----------------
__global__ void cvt_x_kernel(const float* __restrict__ x, __half2* __restrict__ xh) {
    int i = blockIdx.x * blockDim.x + threadIdx.x;      // over N_NODES*D_IN/4
    if (i < N_NODES * D_IN / 4) {
        float4 v = ((const float4*)x)[i];
        xh[i * 2]     = __floats2half2_rn(v.x, v.y);
        xh[i * 2 + 1] = __floats2half2_rn(v.z, v.w);
    }
}

// W [K][128] fp32 -> Wt [128][K] fp16
__global__ void transpose_cvt_kernel(const float* __restrict__ W, __half* __restrict__ Wt, int K) {
    __shared__ float t[16][17];
    int n = blockIdx.x * 16 + threadIdx.x;
    int k = blockIdx.y * 16 + threadIdx.y;
    if (k < K && n < 128) t[threadIdx.y][threadIdx.x] = W[k * 128 + n];
    __syncthreads();
    int n2 = blockIdx.x * 16 + threadIdx.y;
    int k2 = blockIdx.y * 16 + threadIdx.x;
    if (n2 < 128 && k2 < K) Wt[n2 * K + k2] = __float2half(t[threadIdx.x][threadIdx.y]);
}

// ---------------- fp16 mma.sync GEMM with cp.async double buffering ----------------
// C[M,128] = act(A[M,K](half) @ Wt[128,K](half)^T (+bias))
#define SSTR 56                      // halves per smem row (112B: 16B-aligned, conflict-free)
#define BUF_HALVES (128 * SSTR)
#define BUF_BYTES  (BUF_HALVES * 2)

__device__ __forceinline__ uint32_t smem_u32(const void* p) {
    uint32_t a;
    asm("{ .reg .u64 t; cvta.to.shared.u64 t, %1; cvt.u32.u64 %0, t; }" : "=r"(a) : "l"(p));
    return a;
}
__device__ __forceinline__ void cp_async16(uint32_t dst, const void* src, int sz) {
    asm volatile("cp.async.ca.shared.global [%0], [%1], 16, %2;"
                 :: "r"(dst), "l"(src), "r"(sz) : "memory");
}
__device__ __forceinline__ uint32_t lds32(uint32_t addr) {
    uint32_t r;
    asm volatile("ld.shared.b32 %0, [%1];" : "=r"(r) : "r"(addr));
    return r;
}
#define CP_COMMIT() asm volatile("cp.async.commit_group;" ::: "memory")
#define CP_WAIT1()  asm volatile("cp.async.wait_group 1;" ::: "memory")
#define CP_WAIT0()  asm volatile("cp.async.wait_group 0;" ::: "memory")

#define MMA_F16(c, a, b)                                                       \
    asm volatile(                                                              \
        "mma.sync.aligned.m16n8k16.row.col.f32.f16.f16.f32 "                   \
        "{%0,%1,%2,%3}, {%4,%5,%6,%7}, {%8,%9}, {%0,%1,%2,%3};"                \
        : "+f"((c)[0]), "+f"((c)[1]), "+f"((c)[2]), "+f"((c)[3])               \
        : "r"((a)[0]), "r"((a)[1]), "r"((a)[2]), "r"((a)[3]),                  \
          "r"((b)[0]), "r"((b)[1]))

// Block 128x128, BK=32 (NC=K/32 chunks), 256 threads, warp tile 32(M)x64(N).
// blockIdx.y selects (W0,bias0,C0) vs (W1,bias1,C1) when W1 != nullptr.
template <int K>
__global__ void __launch_bounds__(256, 2) gemm_f16_kernel(
    const __half* __restrict__ A,
    const __half* __restrict__ W0, const float* __restrict__ bias0, __half* __restrict__ C0,
    const __half* __restrict__ W1, const float* __restrict__ bias1, __half* __restrict__ C1,
    int M, int do_relu)
{
    const __half* W    = (blockIdx.y == 0) ? W0 : W1;
    const float*  bias = (blockIdx.y == 0) ? bias0 : bias1;
    __half*       C    = (blockIdx.y == 0) ? C0 : C1;

    extern __shared__ __half sm[];
    const uint32_t sA = smem_u32(sm);                    // As[2][BUF]
    const uint32_t sB = sA + 2 * BUF_BYTES;              // Bs[2][BUF]

    const int tid = threadIdx.x;
    const int lane = tid & 31, wid = tid >> 5;
    const int gID = lane >> 2, t4 = lane & 3;
    const int wm = wid & 3, wn = wid >> 2;
    const int m0 = blockIdx.x * 128;
    constexpr int NC = K / 32;

    float acc[2][8][4];
    #pragma unroll
    for (int mi = 0; mi < 2; mi++)
        #pragma unroll
        for (int ni = 0; ni < 8; ni++)
            #pragma unroll
            for (int j = 0; j < 4; j++) acc[mi][ni][j] = 0.f;

    // chunk loader: 128 rows x 32 halves of A and Wt into buffer `buf`
    auto load_chunk = [&](int c, int buf) {
        int k0 = c * 32;
        #pragma unroll
        for (int i = 0; i < 2; i++) {
            int idx = tid + i * 256;
            int row = idx >> 2, seg = idx & 3;
            int g = m0 + row;
            const __half* srcA = A + (long)((g < M) ? g : 0) * K + k0 + seg * 8;
            cp_async16(sA + buf * BUF_BYTES + row * (SSTR * 2) + seg * 16, srcA, (g < M) ? 16 : 0);
            const __half* srcB = W + (long)row * K + k0 + seg * 8;
            cp_async16(sB + buf * BUF_BYTES + row * (SSTR * 2) + seg * 16, srcB, 16);
        }
        CP_COMMIT();
    };

    load_chunk(0, 0);
    load_chunk(1, 1);

    #pragma unroll
    for (int c = 0; c < NC; c++) {
        if (c < NC - 1) CP_WAIT1(); else CP_WAIT0();
        __syncthreads();

        const int buf = c & 1;
        const uint32_t aBase = sA + buf * BUF_BYTES;
        const uint32_t bBase = sB + buf * BUF_BYTES;
        #pragma unroll
        for (int ks = 0; ks < 2; ks++) {
            const int kb = ks * 16;
            uint32_t a[2][4], b[8][2];
            #pragma unroll
            for (int mi = 0; mi < 2; mi++) {
                int r = wm * 32 + mi * 16 + gID;
                uint32_t p = aBase + (r * SSTR + kb + 2 * t4) * 2;
                a[mi][0] = lds32(p);
                a[mi][1] = lds32(p + 8 * SSTR * 2);
                a[mi][2] = lds32(p + 16);
                a[mi][3] = lds32(p + 8 * SSTR * 2 + 16);
            }
            #pragma unroll
            for (int ni = 0; ni < 8; ni++) {
                int n = wn * 64 + ni * 8 + gID;
                uint32_t q = bBase + (n * SSTR + kb + 2 * t4) * 2;
                b[ni][0] = lds32(q);
                b[ni][1] = lds32(q + 16);
            }
            #pragma unroll
            for (int mi = 0; mi < 2; mi++)
                #pragma unroll
                for (int ni = 0; ni < 8; ni++)
                    MMA_F16(acc[mi][ni], a[mi], b[ni]);
        }

        if (c + 2 < NC) {
            __syncthreads();
            load_chunk(c + 2, buf);
        }
    }

    // epilogue (half2 output)
    #pragma unroll
    for (int mi = 0; mi < 2; mi++) {
        int row = m0 + wm * 32 + mi * 16 + gID;
        #pragma unroll
        for (int ni = 0; ni < 8; ni++) {
            int col = wn * 64 + ni * 8 + t4 * 2;
            float bx = 0.f, by = 0.f;
            if (bias) { bx = bias[col]; by = bias[col + 1]; }
            float2 v0 = make_float2(acc[mi][ni][0] + bx, acc[mi][ni][1] + by);
            float2 v1 = make_float2(acc[mi][ni][2] + bx, acc[mi][ni][3] + by);
            if (do_relu) {
                v0.x = fmaxf(v0.x, 0.f); v0.y = fmaxf(v0.y, 0.f);
                v1.x = fmaxf(v1.x, 0.f); v1.y = fmaxf(v1.y, 0.f);
            }
            if (row < M)
                *(__half2*)&C[(long)row * 128 + col] = __floats2half2_rn(v0.x, v0.y);
            if (row + 8 < M)
                *(__half2*)&C[(long)(row + 8) * 128 + col] = __floats2half2_rn(v1.x, v1.y);
        }
    }
}

// ---------------- GCN aggregation: fp16 gather, fp32 accum, fp16 out ----------------
__global__ void agg_kernel(const uint2* __restrict__ xw, const float* __restrict__ bias,
                           uint2* __restrict__ outh) {
    int node = (blockIdx.x * blockDim.x + threadIdx.x) >> 5;
    int lane = threadIdx.x & 31;
    if (node >= N_NODES) return;
    float di = g_dinv[node];
    float sl = di * di;
    uint2 sv = xw[node * 32 + lane];
    float2 s0 = __half22float2(*(__half2*)&sv.x);
    float2 s1 = __half22float2(*(__half2*)&sv.y);
    float4 acc = make_float4(s0.x * sl, s0.y * sl, s1.x * sl, s1.y * sl);
    int p    = g_rowptr[node];
    int pend = g_rowptr[node + 1];
    for (; p < pend; p++) {
        int2 sn = g_csr_sn[p];
        float nm = __int_as_float(sn.y);
        uint2 uv = xw[sn.x * 32 + lane];
        float2 u0 = __half22float2(*(__half2*)&uv.x);
        float2 u1 = __half22float2(*(__half2*)&uv.y);
        acc.x += u0.x * nm; acc.y += u0.y * nm;
        acc.z += u1.x * nm; acc.w += u1.y * nm;
    }
    float4 b = ((const float4*)bias)[lane];
    acc.x = fmaxf(acc.x + b.x, 0.f);
    acc.y = fmaxf(acc.y + b.y, 0.f);
    acc.z = fmaxf(acc.z + b.z, 0.f);
    acc.w = fmaxf(acc.w + b.w, 0.f);
    uint2 o;
    *(__half2*)&o.x = __floats2half2_rn(acc.x, acc.y);
    *(__half2*)&o.y = __floats2half2_rn(acc.z, acc.w);
    outh[node * 32 + lane] = o;
}

// ---------------- edge MLP: warp per dst-node over CSR; A,B in fp16 ----------------
__global__ void edge_kernel(const uint2* __restrict__ Av, const uint2* __restrict__ Bv,
                            const float* __restrict__ Wm2, const float* __restrict__ bm2,
                            float* __restrict__ out) {
    int node = (blockIdx.x * blockDim.x + threadIdx.x) >> 5;
    int lane = threadIdx.x & 31;
    if (node >= N_NODES) return;
    int p    = g_rowptr[node];
    int pend = g_rowptr[node + 1];
    if (p == pend) return;
    uint2 bv = Bv[node * 32 + lane];
    float2 b0 = __half22float2(*(__half2*)&bv.x);
    float2 b1 = __half22float2(*(__half2*)&bv.y);
    float4 w = ((const float4*)Wm2)[lane];
    float bm = bm2[0];
    for (; p < pend; p++) {
        int2 se = g_csr_se[p];
        uint2 av = Av[se.x * 32 + lane];
        float2 a0 = __half22float2(*(__half2*)&av.x);
        float2 a1 = __half22float2(*(__half2*)&av.y);
        float sum = fmaxf(a0.x + b0.x, 0.f) * w.x
                  + fmaxf(a0.y + b0.y, 0.f) * w.y
                  + fmaxf(a1.x + b1.x, 0.f) * w.z
                  + fmaxf(a1.y + b1.y, 0.f) * w.w;
        #pragma unroll
        for (int off = 16; off > 0; off >>= 1)
            sum += __shfl_down_sync(0xffffffff, sum, off);
        if (lane == 0) out[se.y] = sum + bm;
    }
}

// ---------------- launch ----------------
extern "C" void kernel_launch(void* const* d_in, const int* in_sizes, int n_in,
                              void* d_out, int out_size) {
    const float* x      = (const float*)d_in[0];
    const int*   eidx   = (const int*)d_in[1];
    const float* W_in   = (const float*)d_in[2];
    const float* b_in   = (const float*)d_in[3];
    const float* W1     = (const float*)d_in[4];
    const float* b1     = (const float*)d_in[5];
    const float* W2     = (const float*)d_in[6];
    const float* b2     = (const float*)d_in[7];
    const float* Wm1    = (const float*)d_in[8];
    const float* bm1    = (const float*)d_in[9];
    const float* Wm2    = (const float*)d_in[10];
    const float* bm2    = (const float*)d_in[11];
    float* out = (float*)d_out;

    const int* src = eidx;
    const int* dst = eidx + N_EDGES;

    float *buf0f, *buf1f, *buf2f, *buf3f;
    __half *wtin, *wt1, *wt2, *wtm1a, *wtm1b;
    cudaGetSymbolAddress((void**)&buf0f, g_buf0);
    cudaGetSymbolAddress((void**)&buf1f, g_buf1);
    cudaGetSymbolAddress((void**)&buf2f, g_buf2);
    cudaGetSymbolAddress((void**)&buf3f, g_buf3);
    cudaGetSymbolAddress((void**)&wtin, g_wt_in);
    cudaGetSymbolAddress((void**)&wt1, g_wt1);
    cudaGetSymbolAddress((void**)&wt2, g_wt2);
    cudaGetSymbolAddress((void**)&wtm1a, g_wtm1a);
    cudaGetSymbolAddress((void**)&wtm1b, g_wtm1b);

    // half feature arrays packed two-per-float-buffer
    __half* xh   = (__half*)buf3f;
    __half* h0h  = (__half*)buf3f + HALF_OFF;
    __half* xw1h = (__half*)buf0f;
    __half* h1h  = (__half*)buf0f + HALF_OFF;
    __half* xw2h = (__half*)buf1f;
    __half* h2h  = (__half*)buf1f + HALF_OFF;
    __half* Ah   = (__half*)buf2f;
    __half* Bh   = (__half*)buf2f + HALF_OFF;

    static cudaStream_t s2 = nullptr;
    static cudaEvent_t evF = nullptr, evJ = nullptr;
    if (!s2) {
        cudaStreamCreateWithFlags(&s2, cudaStreamNonBlocking);
        cudaEventCreateWithFlags(&evF, cudaEventDisableTiming);
        cudaEventCreateWithFlags(&evJ, cudaEventDisableTiming);
    }

    const int SMEM = 4 * BUF_BYTES;   // 57344 B
    cudaFuncSetAttribute(gemm_f16_kernel<96>,  cudaFuncAttributeMaxDynamicSharedMemorySize, SMEM);
    cudaFuncSetAttribute(gemm_f16_kernel<128>, cudaFuncAttributeMaxDynamicSharedMemorySize, SMEM);

    const int TPB = 256;
    dim3 nodeGrid((N_NODES + TPB - 1) / TPB);
    dim3 edgeGrid((N_EDGES + TPB - 1) / TPB);
    dim3 gemmGrid((N_NODES + 127) / 128, 1);
    dim3 gemmGrid2((N_NODES + 127) / 128, 2);
    dim3 warpNodeGrid((N_NODES * 32 + TPB - 1) / TPB);
    dim3 t16(16, 16);

    // ---- fork: CSR build on s2, concurrent with converts + GEMM1/GEMM2 ----
    cudaEventRecord(evF, 0);
    cudaStreamWaitEvent(s2, evF, 0);

    zero_deg_kernel<<<nodeGrid, TPB, 0, s2>>>();
    hist_kernel<<<edgeGrid, TPB, 0, s2>>>(dst);
    scan1_kernel<<<SCAN_BLOCKS, SCAN_TPB, 0, s2>>>();
    scan2_kernel<<<1, 32, 0, s2>>>();
    scan3_kernel<<<SCAN_BLOCKS, SCAN_TPB, 0, s2>>>();
    fill_kernel<<<edgeGrid, TPB, 0, s2>>>(src, dst);
    cudaEventRecord(evJ, s2);

    // main stream: converts (x -> fp16, W -> fp16 transposed)
    cvt_x_kernel<<<(N_NODES * D_IN / 4 + TPB - 1) / TPB, TPB>>>(x, (__half2*)xh);
    transpose_cvt_kernel<<<dim3(8, 6), t16>>>(W_in, wtin, D_IN);
    transpose_cvt_kernel<<<dim3(8, 8), t16>>>(W1, wt1, HID);
    transpose_cvt_kernel<<<dim3(8, 8), t16>>>(W2, wt2, HID);
    transpose_cvt_kernel<<<dim3(8, 8), t16>>>(Wm1, wtm1a, HID);
    transpose_cvt_kernel<<<dim3(8, 8), t16>>>(Wm1 + HID * HID, wtm1b, HID);

    // h0 = relu(x @ W_in + b_in)            -> h0h
    gemm_f16_kernel<96><<<gemmGrid, 256, SMEM>>>(xh, wtin, b_in, h0h,
                                                 nullptr, nullptr, nullptr, N_NODES, 1);
    // xw1 = h0 @ W1                          -> xw1h
    gemm_f16_kernel<128><<<gemmGrid, 256, SMEM>>>(h0h, wt1, nullptr, xw1h,
                                                  nullptr, nullptr, nullptr, N_NODES, 0);

    // ---- join before first aggregation ----
    cudaStreamWaitEvent(0, evJ, 0);

    // h1 = relu(agg(xw1) + b1)               -> h1h
    agg_kernel<<<warpNodeGrid, TPB>>>((const uint2*)xw1h, b1, (uint2*)h1h);
    // xw2 = h1 @ W2                          -> xw2h
    gemm_f16_kernel<128><<<gemmGrid, 256, SMEM>>>(h1h, wt2, nullptr, xw2h,
                                                  nullptr, nullptr, nullptr, N_NODES, 0);
    // h2 = relu(agg(xw2) + b2)               -> h2h
    agg_kernel<<<warpNodeGrid, TPB>>>((const uint2*)xw2h, b2, (uint2*)h2h);
    // A = h2 @ Wm1a + bm1 -> Ah ;  B = h2 @ Wm1b -> Bh  (one launch, grid.y=2)
    gemm_f16_kernel<128><<<gemmGrid2, 256, SMEM>>>(h2h, wtm1a, bm1, Ah,
                                                   wtm1b, nullptr, Bh, N_NODES, 0);
    // logits per edge (CSR-grouped by dst)
    edge_kernel<<<warpNodeGrid, TPB>>>((const uint2*)Ah, (const uint2*)Bh, Wm2, bm2, out);
}

// round 11
// speedup vs baseline: 1.3644x; 1.0611x over previous
#include <cuda_runtime.h>
#include <cuda_fp16.h>
#include <cstdint>

#define N_NODES 50000
#define N_EDGES 800000
#define D_IN 96
#define HID 128
#define SCAN_TPB 1024
#define SCAN_BLOCKS ((N_NODES + SCAN_TPB - 1) / SCAN_TPB)   // 49
#define HALF_OFF (N_NODES * HID)

// ---------------- scratch (device globals; no allocation allowed) ----------------
__device__ __align__(16) float g_buf0[N_NODES * HID];
__device__ __align__(16) float g_buf1[N_NODES * HID];
__device__ __align__(16) float g_buf2[N_NODES * HID];
__device__ __align__(16) float g_buf3[N_NODES * HID];
__device__ __align__(16) __half g_wt_in[HID * D_IN];
__device__ __align__(16) __half g_wt1[HID * HID];
__device__ __align__(16) __half g_wt2[HID * HID];
__device__ __align__(16) __half g_wtm1a[HID * HID];
__device__ __align__(16) __half g_wtm1b[HID * HID];
__device__ float g_dinv[N_NODES];
__device__ int   g_deg[N_NODES];
__device__ int   g_rowptr[N_NODES + 1];
__device__ int   g_cursor[N_NODES];
__device__ int   g_partials[SCAN_BLOCKS + 1];
__device__ __align__(8) int2 g_csr_sn[N_EDGES];
__device__ __align__(8) int2 g_csr_se[N_EDGES];

// ---------------- graph preprocessing ----------------
__global__ void zero_deg_kernel() {
    int i = blockIdx.x * blockDim.x + threadIdx.x;
    if (i < N_NODES) g_deg[i] = 0;
}

__global__ void hist_kernel(const int* __restrict__ dst) {
    int e = blockIdx.x * blockDim.x + threadIdx.x;
    if (e < N_EDGES) atomicAdd(&g_deg[dst[e]], 1);
}

__global__ void scan1_kernel() {
    __shared__ int ws[32];
    int gid = blockIdx.x * SCAN_TPB + threadIdx.x;
    int lane = threadIdx.x & 31, wid = threadIdx.x >> 5;
    int v = (gid < N_NODES) ? g_deg[gid] : 0;
    if (gid < N_NODES) g_dinv[gid] = rsqrtf((float)(v + 1));
    int x = v;
    #pragma unroll
    for (int off = 1; off < 32; off <<= 1) {
        int t = __shfl_up_sync(0xffffffff, x, off);
        if (lane >= off) x += t;
    }
    if (lane == 31) ws[wid] = x;
    __syncthreads();
    if (wid == 0) {
        int t = ws[lane];
        #pragma unroll
        for (int off = 1; off < 32; off <<= 1) {
            int u = __shfl_up_sync(0xffffffff, t, off);
            if (lane >= off) t += u;
        }
        ws[lane] = t;
    }
    __syncthreads();
    int excl = (wid ? ws[wid - 1] : 0) + x - v;
    if (gid < N_NODES) g_rowptr[gid] = excl;
    if (threadIdx.x == 0) g_partials[blockIdx.x] = ws[31];
}

__global__ void scan2_kernel() {
    int lane = threadIdx.x;
    int v0 = (lane < SCAN_BLOCKS) ? g_partials[lane] : 0;
    int v1 = (lane + 32 < SCAN_BLOCKS) ? g_partials[lane + 32] : 0;
    int x0 = v0;
    #pragma unroll
    for (int off = 1; off < 32; off <<= 1) {
        int t = __shfl_up_sync(0xffffffff, x0, off);
        if (lane >= off) x0 += t;
    }
    int tot0 = __shfl_sync(0xffffffff, x0, 31);
    int x1 = v1;
    #pragma unroll
    for (int off = 1; off < 32; off <<= 1) {
        int t = __shfl_up_sync(0xffffffff, x1, off);
        if (lane >= off) x1 += t;
    }
    if (lane < SCAN_BLOCKS) g_partials[lane] = x0 - v0;
    if (lane + 32 < SCAN_BLOCKS) g_partials[lane + 32] = tot0 + x1 - v1;
    if (lane == 31) g_rowptr[N_NODES] = tot0 + __shfl_sync(0xffffffff, x1, 31);
}

__global__ void scan3_kernel() {
    int gid = blockIdx.x * SCAN_TPB + threadIdx.x;
    if (gid < N_NODES) {
        int r = g_rowptr[gid] + g_partials[blockIdx.x];
        g_rowptr[gid] = r;
        g_cursor[gid] = r;
    }
}

__global__ void fill_kernel(const int* __restrict__ src, const int* __restrict__ dst) {
    int e = blockIdx.x * blockDim.x + threadIdx.x;
    if (e < N_EDGES) {
        int s = src[e], d = dst[e];
        int p = atomicAdd(&g_cursor[d], 1);
        float nm = g_dinv[s] * g_dinv[d];
        g_csr_sn[p] = make_int2(s, __float_as_int(nm));
        g_csr_se[p] = make_int2(s, e);
    }
}

// ---------------- single prep kernel: cvt x -> fp16 AND all 5 weight transposes ----------------
#define CVT_ELEMS (N_NODES * D_IN / 4)
#define CVT_BLOCKS ((CVT_ELEMS + 255) / 256)
__global__ void prep_kernel(const float* __restrict__ x, __half2* __restrict__ xh,
                            const float* __restrict__ W_in, const float* __restrict__ W1,
                            const float* __restrict__ W2, const float* __restrict__ Wm1,
                            __half* __restrict__ wtin, __half* __restrict__ wt1,
                            __half* __restrict__ wt2, __half* __restrict__ wtm1a,
                            __half* __restrict__ wtm1b) {
    __shared__ float t[16][17];
    int b = blockIdx.x, tid = threadIdx.x;
    if (b < CVT_BLOCKS) {
        int i = b * 256 + tid;
        if (i < CVT_ELEMS) {
            float4 v = ((const float4*)x)[i];
            xh[i * 2]     = __floats2half2_rn(v.x, v.y);
            xh[i * 2 + 1] = __floats2half2_rn(v.z, v.w);
        }
        return;
    }
    int tb = b - CVT_BLOCKS;
    const float* W; __half* Wt; int K;
    if (tb < 48)       { W = W_in;            Wt = wtin;  K = 96;  }
    else if (tb < 112) { W = W1;              Wt = wt1;   K = 128; tb -= 48; }
    else if (tb < 176) { W = W2;              Wt = wt2;   K = 128; tb -= 112; }
    else if (tb < 240) { W = Wm1;             Wt = wtm1a; K = 128; tb -= 176; }
    else               { W = Wm1 + HID * HID; Wt = wtm1b; K = 128; tb -= 240; }
    int bx = tb % 8, by = tb / 8;
    int tx = tid & 15, ty = tid >> 4;
    int n = bx * 16 + tx, k = by * 16 + ty;
    if (k < K) t[ty][tx] = W[k * 128 + n];
    __syncthreads();
    int n2 = bx * 16 + ty, k2 = by * 16 + tx;
    if (k2 < K) Wt[n2 * K + k2] = __float2half(t[tx][ty]);
}

// ---------------- fp16 mma.sync GEMM machinery ----------------
#define SSTR 56
#define BUF_HALVES (128 * SSTR)
#define BUF_BYTES  (BUF_HALVES * 2)
#define H0STR 136
#define H0_BYTES (128 * H0STR * 2)

__device__ __forceinline__ uint32_t smem_u32(const void* p) {
    uint32_t a;
    asm("{ .reg .u64 t; cvta.to.shared.u64 t, %1; cvt.u32.u64 %0, t; }" : "=r"(a) : "l"(p));
    return a;
}
__device__ __forceinline__ void cp_async16(uint32_t dst, const void* src, int sz) {
    asm volatile("cp.async.ca.shared.global [%0], [%1], 16, %2;"
                 :: "r"(dst), "l"(src), "r"(sz) : "memory");
}
__device__ __forceinline__ uint32_t lds32(uint32_t addr) {
    uint32_t r;
    asm volatile("ld.shared.b32 %0, [%1];" : "=r"(r) : "r"(addr));
    return r;
}
#define CP_COMMIT() asm volatile("cp.async.commit_group;" ::: "memory")
#define CP_WAIT1()  asm volatile("cp.async.wait_group 1;" ::: "memory")
#define CP_WAIT0()  asm volatile("cp.async.wait_group 0;" ::: "memory")

#define MMA_F16(c, a, b)                                                       \
    asm volatile(                                                              \
        "mma.sync.aligned.m16n8k16.row.col.f32.f16.f16.f32 "                   \
        "{%0,%1,%2,%3}, {%4,%5,%6,%7}, {%8,%9}, {%0,%1,%2,%3};"                \
        : "+f"((c)[0]), "+f"((c)[1]), "+f"((c)[2]), "+f"((c)[3])               \
        : "r"((a)[0]), "r"((a)[1]), "r"((a)[2]), "r"((a)[3]),                  \
          "r"((b)[0]), "r"((b)[1]))

// ---------------- plain GEMM: C[M,128] = act(A[M,128] @ Wt[128,128]^T (+bias)) ----------------
__global__ void __launch_bounds__(256, 2) gemm_f16_kernel(
    const __half* __restrict__ A,
    const __half* __restrict__ W0, const float* __restrict__ bias0, __half* __restrict__ C0,
    const __half* __restrict__ W1, const float* __restrict__ bias1, __half* __restrict__ C1,
    int M, int do_relu)
{
    const __half* W    = (blockIdx.y == 0) ? W0 : W1;
    const float*  bias = (blockIdx.y == 0) ? bias0 : bias1;
    __half*       C    = (blockIdx.y == 0) ? C0 : C1;
    constexpr int K = 128;
    constexpr int NC = 4;

    extern __shared__ __half sm[];
    const uint32_t sA = smem_u32(sm);
    const uint32_t sB = sA + 2 * BUF_BYTES;

    const int tid = threadIdx.x;
    const int lane = tid & 31, wid = tid >> 5;
    const int gID = lane >> 2, t4 = lane & 3;
    const int wm = wid & 3, wn = wid >> 2;
    const int m0 = blockIdx.x * 128;

    float acc[2][8][4];
    #pragma unroll
    for (int mi = 0; mi < 2; mi++)
        #pragma unroll
        for (int ni = 0; ni < 8; ni++)
            #pragma unroll
            for (int j = 0; j < 4; j++) acc[mi][ni][j] = 0.f;

    auto load_chunk = [&](int c, int buf) {
        int k0 = c * 32;
        #pragma unroll
        for (int i = 0; i < 2; i++) {
            int idx = tid + i * 256;
            int row = idx >> 2, seg = idx & 3;
            int g = m0 + row;
            const __half* srcA = A + (long)((g < M) ? g : 0) * K + k0 + seg * 8;
            cp_async16(sA + buf * BUF_BYTES + row * (SSTR * 2) + seg * 16, srcA, (g < M) ? 16 : 0);
            const __half* srcB = W + (long)row * K + k0 + seg * 8;
            cp_async16(sB + buf * BUF_BYTES + row * (SSTR * 2) + seg * 16, srcB, 16);
        }
        CP_COMMIT();
    };

    load_chunk(0, 0);
    load_chunk(1, 1);

    #pragma unroll
    for (int c = 0; c < NC; c++) {
        if (c < NC - 1) CP_WAIT1(); else CP_WAIT0();
        __syncthreads();
        const int buf = c & 1;
        const uint32_t aBase = sA + buf * BUF_BYTES;
        const uint32_t bBase = sB + buf * BUF_BYTES;
        #pragma unroll
        for (int ks = 0; ks < 2; ks++) {
            const int kb = ks * 16;
            uint32_t a[2][4], b[8][2];
            #pragma unroll
            for (int mi = 0; mi < 2; mi++) {
                int r = wm * 32 + mi * 16 + gID;
                uint32_t p = aBase + (r * SSTR + kb + 2 * t4) * 2;
                a[mi][0] = lds32(p);
                a[mi][1] = lds32(p + 8 * SSTR * 2);
                a[mi][2] = lds32(p + 16);
                a[mi][3] = lds32(p + 8 * SSTR * 2 + 16);
            }
            #pragma unroll
            for (int ni = 0; ni < 8; ni++) {
                int n = wn * 64 + ni * 8 + gID;
                uint32_t q = bBase + (n * SSTR + kb + 2 * t4) * 2;
                b[ni][0] = lds32(q);
                b[ni][1] = lds32(q + 16);
            }
            #pragma unroll
            for (int mi = 0; mi < 2; mi++)
                #pragma unroll
                for (int ni = 0; ni < 8; ni++)
                    MMA_F16(acc[mi][ni], a[mi], b[ni]);
        }
        if (c + 2 < NC) {
            __syncthreads();
            load_chunk(c + 2, buf);
        }
    }

    #pragma unroll
    for (int mi = 0; mi < 2; mi++) {
        int row = m0 + wm * 32 + mi * 16 + gID;
        #pragma unroll
        for (int ni = 0; ni < 8; ni++) {
            int col = wn * 64 + ni * 8 + t4 * 2;
            float bx = 0.f, by = 0.f;
            if (bias) { bx = bias[col]; by = bias[col + 1]; }
            float2 v0 = make_float2(acc[mi][ni][0] + bx, acc[mi][ni][1] + by);
            float2 v1 = make_float2(acc[mi][ni][2] + bx, acc[mi][ni][3] + by);
            if (do_relu) {
                v0.x = fmaxf(v0.x, 0.f); v0.y = fmaxf(v0.y, 0.f);
                v1.x = fmaxf(v1.x, 0.f); v1.y = fmaxf(v1.y, 0.f);
            }
            if (row < M)
                *(__half2*)&C[(long)row * 128 + col] = __floats2half2_rn(v0.x, v0.y);
            if (row + 8 < M)
                *(__half2*)&C[(long)(row + 8) * 128 + col] = __floats2half2_rn(v1.x, v1.y);
        }
    }
}

// ---------------- fused GEMM: xw1 = (relu(x@W_in+b_in)) @ W1, h0 kept in smem ----------------
__global__ void __launch_bounds__(256, 2) gemm_fused_kernel(
    const __half* __restrict__ Xh,     // [M, 96]
    const __half* __restrict__ Wt0,    // [128, 96]
    const float* __restrict__ bias0,
    const __half* __restrict__ Wt1,    // [128, 128]
    __half* __restrict__ C,            // xw1 [M, 128]
    int M)
{
    extern __shared__ __half sm[];
    const uint32_t sA = smem_u32(sm);
    const uint32_t sB = sA + 2 * BUF_BYTES;
    const uint32_t sH = sB + 2 * BUF_BYTES;

    const int tid = threadIdx.x;
    const int lane = tid & 31, wid = tid >> 5;
    const int gID = lane >> 2, t4 = lane & 3;
    const int wm = wid & 3, wn = wid >> 2;
    const int m0 = blockIdx.x * 128;

    float acc[2][8][4];
    #pragma unroll
    for (int mi = 0; mi < 2; mi++)
        #pragma unroll
        for (int ni = 0; ni < 8; ni++)
            #pragma unroll
            for (int j = 0; j < 4; j++) acc[mi][ni][j] = 0.f;

    // ===== stage 1: h0 = relu(X @ Wt0^T + b0), K=96 (3 chunks) =====
    auto load1 = [&](int c, int buf) {
        int k0 = c * 32;
        #pragma unroll
        for (int i = 0; i < 2; i++) {
            int idx = tid + i * 256;
            int row = idx >> 2, seg = idx & 3;
            int g = m0 + row;
            const __half* srcA = Xh + (long)((g < M) ? g : 0) * 96 + k0 + seg * 8;
            cp_async16(sA + buf * BUF_BYTES + row * (SSTR * 2) + seg * 16, srcA, (g < M) ? 16 : 0);
            const __half* srcB = Wt0 + (long)row * 96 + k0 + seg * 8;
            cp_async16(sB + buf * BUF_BYTES + row * (SSTR * 2) + seg * 16, srcB, 16);
        }
        CP_COMMIT();
    };

    load1(0, 0);
    load1(1, 1);

    #pragma unroll
    for (int c = 0; c < 3; c++) {
        if (c < 2) CP_WAIT1(); else CP_WAIT0();
        __syncthreads();
        const int buf = c & 1;
        const uint32_t aBase = sA + buf * BUF_BYTES;
        const uint32_t bBase = sB + buf * BUF_BYTES;
        #pragma unroll
        for (int ks = 0; ks < 2; ks++) {
            const int kb = ks * 16;
            uint32_t a[2][4], b[8][2];
            #pragma unroll
            for (int mi = 0; mi < 2; mi++) {
                int r = wm * 32 + mi * 16 + gID;
                uint32_t p = aBase + (r * SSTR + kb + 2 * t4) * 2;
                a[mi][0] = lds32(p);
                a[mi][1] = lds32(p + 8 * SSTR * 2);
                a[mi][2] = lds32(p + 16);
                a[mi][3] = lds32(p + 8 * SSTR * 2 + 16);
            }
            #pragma unroll
            for (int ni = 0; ni < 8; ni++) {
                int n = wn * 64 + ni * 8 + gID;
                uint32_t q = bBase + (n * SSTR + kb + 2 * t4) * 2;
                b[ni][0] = lds32(q);
                b[ni][1] = lds32(q + 16);
            }
            #pragma unroll
            for (int mi = 0; mi < 2; mi++)
                #pragma unroll
                for (int ni = 0; ni < 8; ni++)
                    MMA_F16(acc[mi][ni], a[mi], b[ni]);
        }
        if (c + 2 < 3) {
            __syncthreads();
            load1(c + 2, buf);
        }
    }

    // stage-1 epilogue: bias + relu, write h0 tile to smem
    #pragma unroll
    for (int mi = 0; mi < 2; mi++) {
        int r = wm * 32 + mi * 16 + gID;
        #pragma unroll
        for (int ni = 0; ni < 8; ni++) {
            int col = wn * 64 + ni * 8 + t4 * 2;
            float bx = bias0[col], by = bias0[col + 1];
            __half2 v0 = __floats2half2_rn(fmaxf(acc[mi][ni][0] + bx, 0.f),
                                           fmaxf(acc[mi][ni][1] + by, 0.f));
            __half2 v1 = __floats2half2_rn(fmaxf(acc[mi][ni][2] + bx, 0.f),
                                           fmaxf(acc[mi][ni][3] + by, 0.f));
            *(__half2*)((char*)sm + (sH - smem_u32(sm)) + (r * H0STR + col) * 2)       = v0;
            *(__half2*)((char*)sm + (sH - smem_u32(sm)) + ((r + 8) * H0STR + col) * 2) = v1;
            acc[mi][ni][0] = 0.f; acc[mi][ni][1] = 0.f;
            acc[mi][ni][2] = 0.f; acc[mi][ni][3] = 0.f;
        }
    }

    // ===== RACE FIX: all stage-1 reads of sA/sB must complete before stage-2
    // cp.async overwrites those buffers. This barrier also makes the h0 tile
    // visible to all warps before any stage-2 fragment read. =====
    __syncthreads();

    // ===== stage 2: xw1 = h0(smem) @ Wt1^T, K=128 (4 chunks, B only) =====
    auto load2 = [&](int c, int buf) {
        int k0 = c * 32;
        #pragma unroll
        for (int i = 0; i < 2; i++) {
            int idx = tid + i * 256;
            int row = idx >> 2, seg = idx & 3;
            const __half* srcB = Wt1 + (long)row * 128 + k0 + seg * 8;
            cp_async16(sB + buf * BUF_BYTES + row * (SSTR * 2) + seg * 16, srcB, 16);
        }
        CP_COMMIT();
    };

    load2(0, 0);
    load2(1, 1);

    #pragma unroll
    for (int c = 0; c < 4; c++) {
        if (c < 3) CP_WAIT1(); else CP_WAIT0();
        __syncthreads();
        const int buf = c & 1;
        const int kc = c * 32;
        const uint32_t bBase = sB + buf * BUF_BYTES;
        #pragma unroll
        for (int ks = 0; ks < 2; ks++) {
            const int kb = ks * 16;
            uint32_t a[2][4], b[8][2];
            #pragma unroll
            for (int mi = 0; mi < 2; mi++) {
                int r = wm * 32 + mi * 16 + gID;
                uint32_t p = sH + (r * H0STR + kc + kb + 2 * t4) * 2;
                a[mi][0] = lds32(p);
                a[mi][1] = lds32(p + 8 * H0STR * 2);
                a[mi][2] = lds32(p + 16);
                a[mi][3] = lds32(p + 8 * H0STR * 2 + 16);
            }
            #pragma unroll
            for (int ni = 0; ni < 8; ni++) {
                int n = wn * 64 + ni * 8 + gID;
                uint32_t q = bBase + (n * SSTR + kb + 2 * t4) * 2;
                b[ni][0] = lds32(q);
                b[ni][1] = lds32(q + 16);
            }
            #pragma unroll
            for (int mi = 0; mi < 2; mi++)
                #pragma unroll
                for (int ni = 0; ni < 8; ni++)
                    MMA_F16(acc[mi][ni], a[mi], b[ni]);
        }
        if (c + 2 < 4) {
            __syncthreads();
            load2(c + 2, buf);
        }
    }

    // stage-2 epilogue: write xw1 to gmem
    #pragma unroll
    for (int mi = 0; mi < 2; mi++) {
        int row = m0 + wm * 32 + mi * 16 + gID;
        #pragma unroll
        for (int ni = 0; ni < 8; ni++) {
            int col = wn * 64 + ni * 8 + t4 * 2;
            if (row < M)
                *(__half2*)&C[(long)row * 128 + col] =
                    __floats2half2_rn(acc[mi][ni][0], acc[mi][ni][1]);
            if (row + 8 < M)
                *(__half2*)&C[(long)(row + 8) * 128 + col] =
                    __floats2half2_rn(acc[mi][ni][2], acc[mi][ni][3]);
        }
    }
}

// ---------------- GCN aggregation: fp16 gather, fp32 accum, fp16 out ----------------
__global__ void agg_kernel(const uint2* __restrict__ xw, const float* __restrict__ bias,
                           uint2* __restrict__ outh) {
    int node = (blockIdx.x * blockDim.x + threadIdx.x) >> 5;
    int lane = threadIdx.x & 31;
    if (node >= N_NODES) return;
    float di = g_dinv[node];
    float sl = di * di;
    uint2 sv = xw[node * 32 + lane];
    float2 s0 = __half22float2(*(__half2*)&sv.x);
    float2 s1 = __half22float2(*(__half2*)&sv.y);
    float4 acc = make_float4(s0.x * sl, s0.y * sl, s1.x * sl, s1.y * sl);
    int p    = g_rowptr[node];
    int pend = g_rowptr[node + 1];
    for (; p < pend; p++) {
        int2 sn = g_csr_sn[p];
        float nm = __int_as_float(sn.y);
        uint2 uv = xw[sn.x * 32 + lane];
        float2 u0 = __half22float2(*(__half2*)&uv.x);
        float2 u1 = __half22float2(*(__half2*)&uv.y);
        acc.x += u0.x * nm; acc.y += u0.y * nm;
        acc.z += u1.x * nm; acc.w += u1.y * nm;
    }
    float4 b = ((const float4*)bias)[lane];
    acc.x = fmaxf(acc.x + b.x, 0.f);
    acc.y = fmaxf(acc.y + b.y, 0.f);
    acc.z = fmaxf(acc.z + b.z, 0.f);
    acc.w = fmaxf(acc.w + b.w, 0.f);
    uint2 o;
    *(__half2*)&o.x = __floats2half2_rn(acc.x, acc.y);
    *(__half2*)&o.y = __floats2half2_rn(acc.z, acc.w);
    outh[node * 32 + lane] = o;
}

// ---------------- edge MLP: warp per dst-node over CSR; A,B in fp16 ----------------
__global__ void edge_kernel(const uint2* __restrict__ Av, const uint2* __restrict__ Bv,
                            const float* __restrict__ Wm2, const float* __restrict__ bm2,
                            float* __restrict__ out) {
    int node = (blockIdx.x * blockDim.x + threadIdx.x) >> 5;
    int lane = threadIdx.x & 31;
    if (node >= N_NODES) return;
    int p    = g_rowptr[node];
    int pend = g_rowptr[node + 1];
    if (p == pend) return;
    uint2 bv = Bv[node * 32 + lane];
    float2 b0 = __half22float2(*(__half2*)&bv.x);
    float2 b1 = __half22float2(*(__half2*)&bv.y);
    float4 w = ((const float4*)Wm2)[lane];
    float bm = bm2[0];
    for (; p < pend; p++) {
        int2 se = g_csr_se[p];
        uint2 av = Av[se.x * 32 + lane];
        float2 a0 = __half22float2(*(__half2*)&av.x);
        float2 a1 = __half22float2(*(__half2*)&av.y);
        float sum = fmaxf(a0.x + b0.x, 0.f) * w.x
                  + fmaxf(a0.y + b0.y, 0.f) * w.y
                  + fmaxf(a1.x + b1.x, 0.f) * w.z
                  + fmaxf(a1.y + b1.y, 0.f) * w.w;
        #pragma unroll
        for (int off = 16; off > 0; off >>= 1)
            sum += __shfl_down_sync(0xffffffff, sum, off);
        if (lane == 0) out[se.y] = sum + bm;
    }
}

// ---------------- launch ----------------
extern "C" void kernel_launch(void* const* d_in, const int* in_sizes, int n_in,
                              void* d_out, int out_size) {
    const float* x      = (const float*)d_in[0];
    const int*   eidx   = (const int*)d_in[1];
    const float* W_in   = (const float*)d_in[2];
    const float* b_in   = (const float*)d_in[3];
    const float* W1     = (const float*)d_in[4];
    const float* b1     = (const float*)d_in[5];
    const float* W2     = (const float*)d_in[6];
    const float* b2     = (const float*)d_in[7];
    const float* Wm1    = (const float*)d_in[8];
    const float* bm1    = (const float*)d_in[9];
    const float* Wm2    = (const float*)d_in[10];
    const float* bm2    = (const float*)d_in[11];
    float* out = (float*)d_out;

    const int* src = eidx;
    const int* dst = eidx + N_EDGES;

    float *buf0f, *buf1f, *buf2f, *buf3f;
    __half *wtin, *wt1, *wt2, *wtm1a, *wtm1b;
    cudaGetSymbolAddress((void**)&buf0f, g_buf0);
    cudaGetSymbolAddress((void**)&buf1f, g_buf1);
    cudaGetSymbolAddress((void**)&buf2f, g_buf2);
    cudaGetSymbolAddress((void**)&buf3f, g_buf3);
    cudaGetSymbolAddress((void**)&wtin, g_wt_in);
    cudaGetSymbolAddress((void**)&wt1, g_wt1);
    cudaGetSymbolAddress((void**)&wt2, g_wt2);
    cudaGetSymbolAddress((void**)&wtm1a, g_wtm1a);
    cudaGetSymbolAddress((void**)&wtm1b, g_wtm1b);

    __half* xh   = (__half*)buf3f;
    __half* xw1h = (__half*)buf0f;
    __half* h1h  = (__half*)buf0f + HALF_OFF;
    __half* xw2h = (__half*)buf1f;
    __half* h2h  = (__half*)buf1f + HALF_OFF;
    __half* Ah   = (__half*)buf2f;
    __half* Bh   = (__half*)buf2f + HALF_OFF;

    static cudaStream_t s2 = nullptr;
    static cudaEvent_t evF = nullptr, evJ = nullptr;
    if (!s2) {
        cudaStreamCreateWithFlags(&s2, cudaStreamNonBlocking);
        cudaEventCreateWithFlags(&evF, cudaEventDisableTiming);
        cudaEventCreateWithFlags(&evJ, cudaEventDisableTiming);
    }

    const int SMEM  = 4 * BUF_BYTES;
    const int SMEMF = 4 * BUF_BYTES + H0_BYTES;
    cudaFuncSetAttribute(gemm_f16_kernel,   cudaFuncAttributeMaxDynamicSharedMemorySize, SMEM);
    cudaFuncSetAttribute(gemm_fused_kernel, cudaFuncAttributeMaxDynamicSharedMemorySize, SMEMF);

    const int TPB = 256;
    dim3 nodeGrid((N_NODES + TPB - 1) / TPB);
    dim3 edgeGrid((N_EDGES + TPB - 1) / TPB);
    dim3 gemmGrid((N_NODES + 127) / 128, 1);
    dim3 gemmGrid2((N_NODES + 127) / 128, 2);
    dim3 warpNodeGrid((N_NODES * 32 + TPB - 1) / TPB);

    // ---- fork: CSR build on s2, concurrent with prep + fused GEMM ----
    cudaEventRecord(evF, 0);
    cudaStreamWaitEvent(s2, evF, 0);

    zero_deg_kernel<<<nodeGrid, TPB, 0, s2>>>();
    hist_kernel<<<edgeGrid, TPB, 0, s2>>>(dst);
    scan1_kernel<<<SCAN_BLOCKS, SCAN_TPB, 0, s2>>>();
    scan2_kernel<<<1, 32, 0, s2>>>();
    scan3_kernel<<<SCAN_BLOCKS, SCAN_TPB, 0, s2>>>();
    fill_kernel<<<edgeGrid, TPB, 0, s2>>>(src, dst);
    cudaEventRecord(evJ, s2);

    // main stream: prep (x cvt + all weight transposes) in ONE launch
    prep_kernel<<<CVT_BLOCKS + 48 + 4 * 64, TPB>>>(x, (__half2*)xh, W_in, W1, W2, Wm1,
                                                   wtin, wt1, wt2, wtm1a, wtm1b);

    // xw1 = relu(x@W_in+b_in) @ W1 (fused, h0 stays in smem)
    gemm_fused_kernel<<<gemmGrid, 256, SMEMF>>>(xh, wtin, b_in, wt1, xw1h, N_NODES);

    // ---- join before first aggregation ----
    cudaStreamWaitEvent(0, evJ, 0);

    // h1 = relu(agg(xw1) + b1)
    agg_kernel<<<warpNodeGrid, TPB>>>((const uint2*)xw1h, b1, (uint2*)h1h);
    // xw2 = h1 @ W2
    gemm_f16_kernel<<<gemmGrid, 256, SMEM>>>(h1h, wt2, nullptr, xw2h,
                                             nullptr, nullptr, nullptr, N_NODES, 0);
    // h2 = relu(agg(xw2) + b2)
    agg_kernel<<<warpNodeGrid, TPB>>>((const uint2*)xw2h, b2, (uint2*)h2h);
    // A = h2 @ Wm1a + bm1 ; B = h2 @ Wm1b  (one launch, grid.y = 2)
    gemm_f16_kernel<<<gemmGrid2, 256, SMEM>>>(h2h, wtm1a, bm1, Ah,
                                              wtm1b, nullptr, Bh, N_NODES, 0);
    // logits per edge
    edge_kernel<<<warpNodeGrid, TPB>>>((const uint2*)Ah, (const uint2*)Bh, Wm2, bm2, out);
}